// round 5
// baseline (speedup 1.0000x reference)
#include <cuda_runtime.h>
#include <math.h>

// Problem constants (fixed shapes for this problem instance)
#define NN   1024     // notes
#define LL   32768    // max note length
#define WW   1024     // hann window length
#define HH   8        // harmonics
#define KK   128      // FIR taps
#define TILE 2048     // output samples per block
#define NTHREADS 256
#define OPT  8        // outputs per thread (TILE = NTHREADS*OPT)

typedef unsigned long long ull;

// Scratch (device globals; no allocation allowed)
__device__ float g_amps[NN * HH];   // softplus(z) * vel, per note per harmonic
__device__ float g_hann[WW];
__device__ int   g_olen[NN];

// ---------------------------------------------------------------------------
// Packed f32x2 helpers (Blackwell FFMA2/FADD2/FMUL2 — only reachable via PTX)
// ---------------------------------------------------------------------------
__device__ __forceinline__ ull pack2(float lo, float hi) {
    ull r;
    asm("mov.b64 %0, {%1, %2};" : "=l"(r) : "f"(lo), "f"(hi));
    return r;
}
__device__ __forceinline__ void unpack2(ull v, float& lo, float& hi) {
    asm("mov.b64 {%0, %1}, %2;" : "=f"(lo), "=f"(hi) : "l"(v));
}
__device__ __forceinline__ ull fma2(ull a, ull b, ull c) {
    ull d;
    asm("fma.rn.f32x2 %0, %1, %2, %3;" : "=l"(d) : "l"(a), "l"(b), "l"(c));
    return d;
}
__device__ __forceinline__ ull mul2(ull a, ull b) {
    ull d;
    asm("mul.rn.f32x2 %0, %1, %2;" : "=l"(d) : "l"(a), "l"(b));
    return d;
}
__device__ __forceinline__ ull add2(ull a, ull b) {
    ull d;
    asm("add.rn.f32x2 %0, %1, %2;" : "=l"(d) : "l"(a), "l"(b));
    return d;
}

// ---------------------------------------------------------------------------
// Scalar accurate sin (prep / reference path). Cody-Waite + sin.approx.
// ---------------------------------------------------------------------------
__device__ __forceinline__ float sin_ref(float x) {
    const float INV2PI = 0.15915494309189535f;
    float k = rintf(x * INV2PI);
    float r = fmaf(k, -6.28125f, x);
    r = fmaf(k, -1.9359588623046875e-3f, r);
    r = fmaf(k,  6.5168271821061e-7f,  r);
    return __sinf(r);
}

// Accurate-enough tanh, flag-independent (avoid tanh.approx ~2^-10 error).
__device__ __forceinline__ float tanh_ref(float x) {
    float ax = fabsf(x);
    float r;
    if (ax >= 9.0f) {
        r = 1.0f;
    } else {
        float e = __expf(2.0f * ax);
        r = 1.0f - __fdividef(2.0f, e + 1.0f);
    }
    return copysignf(r, x);
}

// ---------------------------------------------------------------------------
// Prep kernel: per-note MLPs (time latent -> amps), hann table.
// ---------------------------------------------------------------------------
__global__ void prep_kernel(
    const float* __restrict__ freq, const float* __restrict__ velocity,
    const float* __restrict__ w1,  const float* __restrict__ b1,
    const float* __restrict__ w2,  const float* __restrict__ b2,
    const float* __restrict__ ws1, const float* __restrict__ bs1,
    const float* __restrict__ ws2, const float* __restrict__ bs2,
    const int*   __restrict__ starts, const int* __restrict__ lengths,
    int D)
{
    int i = blockIdx.x * blockDim.x + threadIdx.x;

    if (i < WW) {
        // exactly replicate reference arg: fl(fl(2pi_f32 * n) / 1024)
        float a = 6.283185307179586f * (float)i * (1.0f / 1024.0f);
        double c = cos((double)a);
        g_hann[i] = 0.5f * (1.0f - (float)c);
    }

    if (i < NN) {
        int st = starts[i];
        int en = st + lengths[i];
        int ol = min(en, D) - st;
        ol = max(0, min(ol, LL));
        g_olen[i] = ol;

        // time embedder: Linear(1,32) -> ReLU -> Linear(32,2)
        float nt = (float)st / (float)D;
        float lat0 = b2[0], lat1 = b2[1];
        #pragma unroll 8
        for (int j = 0; j < 32; ++j) {
            float h = fmaxf(fmaf(nt, w1[j], b1[j]), 0.0f);
            lat0 = fmaf(h, w2[j * 2 + 0], lat0);
            lat1 = fmaf(h, w2[j * 2 + 1], lat1);
        }

        float vel = velocity[i] * (1.0f / 127.0f);
        float feat0 = freq[i], feat1 = vel;

        // synth MLP: (4 -> 64 -> 8), softplus on output
        float z[HH];
        #pragma unroll
        for (int h = 0; h < HH; ++h) z[h] = bs2[h];
        #pragma unroll 4
        for (int j = 0; j < 64; ++j) {
            float h2 = bs1[j];
            h2 = fmaf(feat0, ws1[0 * 64 + j], h2);
            h2 = fmaf(feat1, ws1[1 * 64 + j], h2);
            h2 = fmaf(lat0,  ws1[2 * 64 + j], h2);
            h2 = fmaf(lat1,  ws1[3 * 64 + j], h2);
            h2 = fmaxf(h2, 0.0f);
            #pragma unroll
            for (int h = 0; h < HH; ++h)
                z[h] = fmaf(h2, ws2[j * HH + h], z[h]);
        }
        #pragma unroll
        for (int h = 0; h < HH; ++h) {
            float zz = z[h];
            float sp = fmaxf(zz, 0.0f) + log1pf(__expf(-fabsf(zz)));
            g_amps[i * HH + h] = sp * vel;            // fold vel into amps
        }
    }
}

// ---------------------------------------------------------------------------
// Zero the output (harness poisons d_out). Vectorized float4.
// ---------------------------------------------------------------------------
__global__ void zero_kernel(float4* __restrict__ out4, int n4, float* __restrict__ out, int n) {
    int i = blockIdx.x * blockDim.x + threadIdx.x;
    if (i < n4) out4[i] = make_float4(0.f, 0.f, 0.f, 0.f);
    int tail = n4 * 4 + i;
    if (tail < n && i < 4) out[tail] = 0.0f;
}

// ---------------------------------------------------------------------------
// Main kernel.
// Phase 1: packed-f32x2 synthesis of the windowed/masked segment into smem
//          (lanewise bit-identical to scalar: mul.rn/fma.rn per lane; rint
//          via magic-constant add/sub, exact for |k| < 2^22).
// Phase 2: 128-tap FIR via static 16-reg window (no per-tap shifting),
//          8 taps per group, packed FFMA2, then tanh + RED.ADD scatter.
//
// jax conv is CROSS-CORRELATION with left pad (K-1):
//   y[r] = sum_{k=0..127} fir[k] * s[r + k]   (UNREVERSED fir)
// ---------------------------------------------------------------------------
#define IDX9(i) ((i) + ((i) >> 3))
#define SEG_EXT (TILE + 128)                 // s indices [0, TILE+127]

__global__ void __launch_bounds__(NTHREADS)
synth_kernel(const float* __restrict__ freq,
             const int*   __restrict__ starts,
             const float* __restrict__ fir,
             float*       __restrict__ out)
{
    const int note = blockIdx.y;
    const int olen = g_olen[note];
    const int t0   = blockIdx.x * TILE;
    if (t0 >= olen) return;                  // uniform early exit

    __shared__ float s_seg[SEG_EXT + (SEG_EXT >> 3)];      // 2448 floats
    __shared__ ull s_fir2[KK];                             // (fir[k], fir[k])

    const int tid = threadIdx.x;
    if (tid < KK) {
        float g = __ldg(&fir[tid]);          // UNREVERSED tap
        s_fir2[tid] = pack2(g, g);
    }

    // per-note constants (uniform loads)
    const float f0 = __ldg(&freq[note]);
    const int   start = __ldg(&starts[note]);
    ull amp2[HH];
    #pragma unroll
    for (int h = 0; h < HH; ++h) {
        float a = __ldg(&g_amps[note * HH + h]);
        amp2[h] = pack2(a, a);
    }

    // ---- phase 1: packed synthesis, 2 samples per iteration ----
    const int wstart = olen - WW;
    const ull f02     = pack2(f0, f0);
    const ull inv2pi2 = pack2(0.15915494309189535f, 0.15915494309189535f);
    const ull magic2  = pack2(12582912.0f, 12582912.0f);       // 1.5 * 2^23
    const ull nmagic2 = pack2(-12582912.0f, -12582912.0f);
    const ull nC1_2   = pack2(-6.28125f, -6.28125f);
    const ull nC2_2   = pack2(-1.9359588623046875e-3f, -1.9359588623046875e-3f);
    const ull pC3_2   = pack2(6.5168271821061e-7f, 6.5168271821061e-7f);

    for (int p = tid; p < SEG_EXT / 2; p += NTHREADS) {
        const int e = 2 * p;
        const int t = t0 - 127 + e;
        float ft = (float)t;                    // exact (|t| < 2^24)
        ull ft2 = pack2(ft, ft + 1.0f);         // exact integers
        ull ph2 = mul2(f02, ft2);               // = fl(f*t) per lane (ref)
        ull acc2 = pack2(0.0f, 0.0f);
        #pragma unroll
        for (int h = 1; h <= HH; ++h) {
            ull h2c  = pack2((float)h, (float)h);
            ull arg2 = mul2(h2c, ph2);          // fl(h*phase) per lane (ref)
            ull u2 = fma2(arg2, inv2pi2, magic2);
            ull k2 = add2(u2, nmagic2);         // rint(arg/2pi), RN-even
            ull r2 = fma2(k2, nC1_2, arg2);
            r2 = fma2(k2, nC2_2, r2);
            r2 = fma2(k2, pC3_2, r2);
            float rl, rh;
            unpack2(r2, rl, rh);
            ull s2 = pack2(__sinf(rl), __sinf(rh));
            acc2 = fma2(amp2[h - 1], s2, acc2);
        }
        float a0, a1;
        unpack2(acc2, a0, a1);
        // lane 0 post: mask + window
        if ((unsigned)t >= (unsigned)olen) a0 = 0.0f;
        else { int wp = t - wstart; if (wp >= 0) a0 *= g_hann[wp]; }
        // lane 1 post
        int t1 = t + 1;
        if ((unsigned)t1 >= (unsigned)olen) a1 = 0.0f;
        else { int wp = t1 - wstart; if (wp >= 0) a1 *= g_hann[wp]; }
        s_seg[IDX9(e)]     = a0;
        s_seg[IDX9(e + 1)] = a1;
    }
    __syncthreads();

    // ---- phase 2: FIR via static window + FFMA2, tanh, scatter ----
    const int limit = olen - t0;             // valid outputs: r < limit
    const int r0 = tid * OPT;
    if (r0 < limit) {
        ull acc2[4];
        #pragma unroll
        for (int q = 0; q < 4; ++q) acc2[q] = pack2(0.0f, 0.0f);

        float v[16];
        #pragma unroll
        for (int i = 0; i < 8; ++i) v[i] = s_seg[IDX9(r0 + i)];

        #pragma unroll 2
        for (int k = 0; k < KK; k += 8) {
            // refill upper half of the window
            #pragma unroll
            for (int i = 0; i < 8; ++i) v[8 + i] = s_seg[IDX9(r0 + k + 8 + i)];
            // pre-pack adjacent pairs P[j] = (v[j], v[j+1]), j = 0..13
            ull P[14];
            #pragma unroll
            for (int j = 0; j < 14; ++j) P[j] = pack2(v[j], v[j + 1]);
            // 8 taps, 4 output-pairs each: y[2q],y[2q+1] += fir[k+i]*v[2q+i..]
            #pragma unroll
            for (int i = 0; i < 8; ++i) {
                ull g2 = s_fir2[k + i];          // LDS.64 broadcast
                #pragma unroll
                for (int q = 0; q < 4; ++q)
                    acc2[q] = fma2(g2, P[2 * q + i], acc2[q]);
            }
            // slide window by 8
            #pragma unroll
            for (int i = 0; i < 8; ++i) v[i] = v[8 + i];
        }

        float acc[OPT];
        #pragma unroll
        for (int q = 0; q < 4; ++q) unpack2(acc2[q], acc[2 * q], acc[2 * q + 1]);

        float* __restrict__ gout = out + start + t0 + r0;
        #pragma unroll
        for (int m = 0; m < OPT; ++m) {
            if (r0 + m < limit)
                atomicAdd(gout + m, tanh_ref(acc[m]));   // compiles to RED.ADD
        }
    }
}

// ---------------------------------------------------------------------------
// Launch: zero -> prep -> synth (same stream, graph-capturable)
// ---------------------------------------------------------------------------
extern "C" void kernel_launch(void* const* d_in, const int* in_sizes, int n_in,
                              void* d_out, int out_size) {
    const float* freq     = (const float*)d_in[0];
    const float* velocity = (const float*)d_in[1];
    const float* w1       = (const float*)d_in[2];
    const float* b1       = (const float*)d_in[3];
    const float* w2       = (const float*)d_in[4];
    const float* b2       = (const float*)d_in[5];
    const float* ws1      = (const float*)d_in[6];
    const float* bs1      = (const float*)d_in[7];
    const float* ws2      = (const float*)d_in[8];
    const float* bs2      = (const float*)d_in[9];
    const float* fir      = (const float*)d_in[10];
    const int*   starts   = (const int*)d_in[11];
    const int*   lengths  = (const int*)d_in[12];
    float* out = (float*)d_out;
    const int D = out_size;                  // duration_samples == out_size

    int n4 = D / 4;
    zero_kernel<<<(n4 + 511) / 512, 512>>>((float4*)out, n4, out, D);
    prep_kernel<<<4, 256>>>(freq, velocity, w1, b1, w2, b2,
                            ws1, bs1, ws2, bs2, starts, lengths, D);
    dim3 grid(LL / TILE, NN);                // 16 x 1024 blocks, early-exit culls
    synth_kernel<<<grid, NTHREADS>>>(freq, starts, fir, out);
}

// round 6
// speedup vs baseline: 1.0237x; 1.0237x over previous
#include <cuda_runtime.h>
#include <cuda_bf16.h>
#include <math.h>

// Problem constants (fixed shapes for this problem instance)
#define NN   1024     // notes
#define LL   32768    // max note length
#define WW   1024     // hann window length
#define HH   8        // harmonics
#define KK   128      // FIR taps
#define TILE 2048     // output samples per block
#define NTHREADS 256
#define OPT  8        // outputs per thread in epilogue

#define SEG   2176    // s indices [0, 2175]: covers b*16 + j, b<128, j<144
#define KPAD  144     // FIR K padded to 9 k-steps of 16

// Scratch (device globals; no allocation allowed)
__device__ float g_amps[NN * HH];   // softplus(z) * vel, per note per harmonic
__device__ float g_hann[WW];
__device__ int   g_olen[NN];

// ---------------------------------------------------------------------------
// Accurate sin of an fp32 argument, |x| < ~1e5 (Cody-Waite 3-term + MUFU).
// ---------------------------------------------------------------------------
__device__ __forceinline__ float sin_ref(float x) {
    const float INV2PI = 0.15915494309189535f;
    float k = rintf(x * INV2PI);
    float r = fmaf(k, -6.28125f, x);
    r = fmaf(k, -1.9359588623046875e-3f, r);
    r = fmaf(k,  6.5168271821061e-7f,  r);
    return __sinf(r);
}

// Accurate-enough tanh, flag-independent (avoid tanh.approx ~2^-10 error).
__device__ __forceinline__ float tanh_ref(float x) {
    float ax = fabsf(x);
    float r;
    if (ax >= 9.0f) {
        r = 1.0f;
    } else {
        float e = __expf(2.0f * ax);
        r = 1.0f - __fdividef(2.0f, e + 1.0f);
    }
    return copysignf(r, x);
}

// hi/lo bf16 split: hi = truncate-to-bf16 (exact), lo = rn-bf16(x - hi)
__device__ __forceinline__ void split_bf16(float x, unsigned short& h, unsigned short& l) {
    unsigned int xb = __float_as_uint(x);
    h = (unsigned short)(xb >> 16);
    float hf = __uint_as_float(xb & 0xFFFF0000u);
    float lf = x - hf;                        // exact
    __nv_bfloat16 lb = __float2bfloat16(lf);  // rn
    l = *(unsigned short*)&lb;
}

// ---------------------------------------------------------------------------
// Prep kernel: per-note MLPs (time latent -> amps), hann table.
// ---------------------------------------------------------------------------
__global__ void prep_kernel(
    const float* __restrict__ freq, const float* __restrict__ velocity,
    const float* __restrict__ w1,  const float* __restrict__ b1,
    const float* __restrict__ w2,  const float* __restrict__ b2,
    const float* __restrict__ ws1, const float* __restrict__ bs1,
    const float* __restrict__ ws2, const float* __restrict__ bs2,
    const int*   __restrict__ starts, const int* __restrict__ lengths,
    int D)
{
    int i = blockIdx.x * blockDim.x + threadIdx.x;

    if (i < WW) {
        // exactly replicate reference arg: fl(fl(2pi_f32 * n) / 1024)
        float a = 6.283185307179586f * (float)i * (1.0f / 1024.0f);
        double c = cos((double)a);
        g_hann[i] = 0.5f * (1.0f - (float)c);
    }

    if (i < NN) {
        int st = starts[i];
        int en = st + lengths[i];
        int ol = min(en, D) - st;
        ol = max(0, min(ol, LL));
        g_olen[i] = ol;

        // time embedder: Linear(1,32) -> ReLU -> Linear(32,2)
        float nt = (float)st / (float)D;
        float lat0 = b2[0], lat1 = b2[1];
        #pragma unroll 8
        for (int j = 0; j < 32; ++j) {
            float h = fmaxf(fmaf(nt, w1[j], b1[j]), 0.0f);
            lat0 = fmaf(h, w2[j * 2 + 0], lat0);
            lat1 = fmaf(h, w2[j * 2 + 1], lat1);
        }

        float vel = velocity[i] * (1.0f / 127.0f);
        float feat0 = freq[i], feat1 = vel;

        // synth MLP: (4 -> 64 -> 8), softplus on output
        float z[HH];
        #pragma unroll
        for (int h = 0; h < HH; ++h) z[h] = bs2[h];
        #pragma unroll 4
        for (int j = 0; j < 64; ++j) {
            float h2 = bs1[j];
            h2 = fmaf(feat0, ws1[0 * 64 + j], h2);
            h2 = fmaf(feat1, ws1[1 * 64 + j], h2);
            h2 = fmaf(lat0,  ws1[2 * 64 + j], h2);
            h2 = fmaf(lat1,  ws1[3 * 64 + j], h2);
            h2 = fmaxf(h2, 0.0f);
            #pragma unroll
            for (int h = 0; h < HH; ++h)
                z[h] = fmaf(h2, ws2[j * HH + h], z[h]);
        }
        #pragma unroll
        for (int h = 0; h < HH; ++h) {
            float zz = z[h];
            float sp = fmaxf(zz, 0.0f) + log1pf(__expf(-fabsf(zz)));
            g_amps[i * HH + h] = sp * vel;            // fold vel into amps
        }
    }
}

// ---------------------------------------------------------------------------
// Zero the output (harness poisons d_out). Vectorized float4.
// ---------------------------------------------------------------------------
__global__ void zero_kernel(float4* __restrict__ out4, int n4, float* __restrict__ out, int n) {
    int i = blockIdx.x * blockDim.x + threadIdx.x;
    if (i < n4) out4[i] = make_float4(0.f, 0.f, 0.f, 0.f);
    int tail = n4 * 4 + i;
    if (tail < n && i < 4) out[tail] = 0.0f;
}

// ---------------------------------------------------------------------------
// Main kernel.
// Phase 0: build Toeplitz FIR matrix Fe[p][j] = fir[j-p] (16 x 144), hi/lo bf16.
// Phase 1: scalar synthesis of windowed/masked segment (bit-identical to the
//          R1 path), stored as hi/lo bf16 split arrays.
// Phase 2: FIR as tensor-core GEMM: y[b*16+p] = sum_j Fe[p][j] * s[b*16+j]
//          via mma.sync.m16n8k16 (bf16 -> fp32), 3 split products (hh,hl,lh).
//          Each warp handles 2 n-groups of 8 blocks; results staged in smem.
// Phase 3: coalesced tanh + RED.ADD scatter.
//
// jax conv is CROSS-CORRELATION with left pad (K-1):
//   y[r] = sum_{k=0..127} fir[k] * s[r + k],  s[e] = x(t0 - 127 + e)
// ---------------------------------------------------------------------------
__device__ __forceinline__ void mma_bf16(float& d0, float& d1, float& d2, float& d3,
                                         unsigned int a0, unsigned int a1,
                                         unsigned int a2, unsigned int a3,
                                         unsigned int b0, unsigned int b1) {
    asm volatile(
        "mma.sync.aligned.m16n8k16.row.col.f32.bf16.bf16.f32 "
        "{%0,%1,%2,%3}, {%4,%5,%6,%7}, {%8,%9}, {%0,%1,%2,%3};"
        : "+f"(d0), "+f"(d1), "+f"(d2), "+f"(d3)
        : "r"(a0), "r"(a1), "r"(a2), "r"(a3), "r"(b0), "r"(b1));
}

__global__ void __launch_bounds__(NTHREADS)
synth_kernel(const float* __restrict__ freq,
             const int*   __restrict__ starts,
             const float* __restrict__ fir,
             float*       __restrict__ out)
{
    const int note = blockIdx.y;
    const int olen = g_olen[note];
    const int t0   = blockIdx.x * TILE;
    if (t0 >= olen) return;                  // uniform early exit

    __shared__ unsigned short s_h[SEG], s_l[SEG];          // segment hi/lo bf16
    __shared__ unsigned short feh[16 * KPAD], fel[16 * KPAD];
    __shared__ float y_s[TILE];

    const int tid = threadIdx.x;

    // ---- phase 0: Toeplitz FIR matrix, split bf16 ----
    for (int idx = tid; idx < 16 * KPAD; idx += NTHREADS) {
        int p = idx / KPAD, j = idx - p * KPAD;
        int d = j - p;
        float v = (d >= 0 && d < KK) ? __ldg(&fir[d]) : 0.0f;
        unsigned short h, l;
        split_bf16(v, h, l);
        feh[idx] = h;
        fel[idx] = l;
    }

    // per-note constants (uniform loads)
    const float f0 = __ldg(&freq[note]);
    const int   start = __ldg(&starts[note]);
    float amp[HH];
    #pragma unroll
    for (int h = 0; h < HH; ++h) amp[h] = __ldg(&g_amps[note * HH + h]);

    // ---- phase 1: synthesize windowed/masked segment, split bf16 ----
    const int wstart = olen - WW;
    for (int e = tid; e < SEG; e += NTHREADS) {
        int t = t0 - 127 + e;
        float v = 0.0f;
        if (t >= 0 && t < olen) {
            float ph = f0 * (float)t;        // matches ref fp32 phase
            float acc = 0.0f;
            #pragma unroll
            for (int h = 1; h <= HH; ++h) {
                float arg = (float)h * ph;   // matches ref fl(h*phase)
                acc = fmaf(amp[h - 1], sin_ref(arg), acc);
            }
            int wpos = t - wstart;
            if (wpos >= 0) acc *= g_hann[wpos];   // wpos < WW guaranteed
            v = acc;
        }
        unsigned short hh, ll;
        split_bf16(v, hh, ll);
        s_h[e] = hh;
        s_l[e] = ll;
    }
    __syncthreads();

    // ---- phase 2: FIR via mma.sync, 2 n-groups of 8 blocks per warp ----
    {
        const int lane = tid & 31;
        const int w    = tid >> 5;
        const int rr   = lane >> 2;          // 0..7 (A row / B col group)
        const int kq   = (lane & 3) << 1;    // 0,2,4,6 (k pair offset)

        #pragma unroll
        for (int g2 = 0; g2 < 2; ++g2) {
            const int g = w * 2 + g2;        // n-group: blocks g*8 .. g*8+7
            float d0 = 0.f, d1 = 0.f, d2 = 0.f, d3 = 0.f;
            const int bbase = g * 128 + rr * 16;   // + 16q + k

            #pragma unroll
            for (int q = 0; q < 9; ++q) {
                const int ja = q * 16 + kq;
                // A fragments (Fe): rows rr / rr+8, k pairs ja / ja+8
                unsigned int ah0 = *(const unsigned int*)&feh[ rr      * KPAD + ja];
                unsigned int ah1 = *(const unsigned int*)&feh[(rr + 8) * KPAD + ja];
                unsigned int ah2 = *(const unsigned int*)&feh[ rr      * KPAD + ja + 8];
                unsigned int ah3 = *(const unsigned int*)&feh[(rr + 8) * KPAD + ja + 8];
                unsigned int al0 = *(const unsigned int*)&fel[ rr      * KPAD + ja];
                unsigned int al1 = *(const unsigned int*)&fel[(rr + 8) * KPAD + ja];
                unsigned int al2 = *(const unsigned int*)&fel[ rr      * KPAD + ja + 8];
                unsigned int al3 = *(const unsigned int*)&fel[(rr + 8) * KPAD + ja + 8];
                // B fragments (segment): col rr, k pairs ja / ja+8
                unsigned int bh0 = *(const unsigned int*)&s_h[bbase + ja];
                unsigned int bh1 = *(const unsigned int*)&s_h[bbase + ja + 8];
                unsigned int bl0 = *(const unsigned int*)&s_l[bbase + ja];
                unsigned int bl1 = *(const unsigned int*)&s_l[bbase + ja + 8];

                mma_bf16(d0, d1, d2, d3, ah0, ah1, ah2, ah3, bh0, bh1);  // hh
                mma_bf16(d0, d1, d2, d3, ah0, ah1, ah2, ah3, bl0, bl1);  // hl
                mma_bf16(d0, d1, d2, d3, al0, al1, al2, al3, bh0, bh1);  // lh
            }
            // D frag: row p = rr (+8), col n = (lane&3)*2 (+1)
            // y index = (g*8 + n)*16 + p
            const int col = (lane & 3) << 1;
            const int base = (g * 8 + col) * 16 + rr;
            y_s[base]      = d0;     // (p=rr,   n=col)
            y_s[base + 16] = d1;     // (p=rr,   n=col+1)
            y_s[base + 8]  = d2;     // (p=rr+8, n=col)
            y_s[base + 24] = d3;     // (p=rr+8, n=col+1)
        }
    }
    __syncthreads();

    // ---- phase 3: coalesced tanh + scatter-add ----
    const int limit = olen - t0;             // valid outputs: r < limit
    const int r0 = tid * OPT;
    if (r0 < limit) {
        float* __restrict__ gout = out + start + t0 + r0;
        #pragma unroll
        for (int m = 0; m < OPT; ++m) {
            if (r0 + m < limit)
                atomicAdd(gout + m, tanh_ref(y_s[r0 + m]));   // RED.ADD
        }
    }
}

// ---------------------------------------------------------------------------
// Launch: zero -> prep -> synth (same stream, graph-capturable)
// ---------------------------------------------------------------------------
extern "C" void kernel_launch(void* const* d_in, const int* in_sizes, int n_in,
                              void* d_out, int out_size) {
    const float* freq     = (const float*)d_in[0];
    const float* velocity = (const float*)d_in[1];
    const float* w1       = (const float*)d_in[2];
    const float* b1       = (const float*)d_in[3];
    const float* w2       = (const float*)d_in[4];
    const float* b2       = (const float*)d_in[5];
    const float* ws1      = (const float*)d_in[6];
    const float* bs1      = (const float*)d_in[7];
    const float* ws2      = (const float*)d_in[8];
    const float* bs2      = (const float*)d_in[9];
    const float* fir      = (const float*)d_in[10];
    const int*   starts   = (const int*)d_in[11];
    const int*   lengths  = (const int*)d_in[12];
    float* out = (float*)d_out;
    const int D = out_size;                  // duration_samples == out_size

    int n4 = D / 4;
    zero_kernel<<<(n4 + 511) / 512, 512>>>((float4*)out, n4, out, D);
    prep_kernel<<<4, 256>>>(freq, velocity, w1, b1, w2, b2,
                            ws1, bs1, ws2, bs2, starts, lengths, D);
    dim3 grid(LL / TILE, NN);                // 16 x 1024 blocks, early-exit culls
    synth_kernel<<<grid, NTHREADS>>>(freq, starts, fir, out);
}

// round 7
// speedup vs baseline: 1.4735x; 1.4393x over previous
#include <cuda_runtime.h>
#include <cuda_bf16.h>
#include <math.h>

// Problem constants (fixed shapes for this problem instance)
#define NN   1024     // notes
#define LL   32768    // max note length
#define WW   1024     // hann window length
#define HH   8        // harmonics
#define KK   128      // FIR taps
#define TILE 2048     // output samples per block
#define NTHREADS 256
#define OPT  8        // outputs per thread in epilogue

#define SEG   2176    // s indices [0, 2175]: covers b*16 + j, b<128, j<144
#define KPAD  144     // FIR K padded to 9 k-steps of 16

// Scratch (device globals; no allocation allowed)
__device__ float g_amps[NN * HH];   // softplus(z) * vel, per note per harmonic
__device__ float g_hann[WW];
__device__ int   g_olen[NN];

// ---------------------------------------------------------------------------
// Accurate sin of an fp32 argument, |x| < ~1e5.
// k via magic-constant RN-even round (no FRND), 3-term Cody-Waite, MUFU sin.
// ---------------------------------------------------------------------------
__device__ __forceinline__ float sin_ref(float x) {
    const float INV2PI = 0.15915494309189535f;
    const float MAGIC  = 12582912.0f;                 // 1.5 * 2^23
    float k = fmaf(x, INV2PI, MAGIC) - MAGIC;         // rint-even(x/2pi)
    float r = fmaf(k, -6.28125f, x);
    r = fmaf(k, -1.9359588623046875e-3f, r);
    r = fmaf(k,  6.5168271821061e-7f,  r);
    return __sinf(r);
}

// Accurate-enough tanh, flag-independent (avoid tanh.approx ~2^-10 error).
__device__ __forceinline__ float tanh_ref(float x) {
    float ax = fabsf(x);
    float r;
    if (ax >= 9.0f) {
        r = 1.0f;
    } else {
        float e = __expf(2.0f * ax);
        r = 1.0f - __fdividef(2.0f, e + 1.0f);
    }
    return copysignf(r, x);
}

// hi/lo bf16 split: hi = truncate-to-bf16 (exact), lo = rn-bf16(x - hi)
__device__ __forceinline__ void split_bf16(float x, unsigned short& h, unsigned short& l) {
    unsigned int xb = __float_as_uint(x);
    h = (unsigned short)(xb >> 16);
    float hf = __uint_as_float(xb & 0xFFFF0000u);
    float lf = x - hf;                        // exact
    __nv_bfloat16 lb = __float2bfloat16(lf);  // rn
    l = *(unsigned short*)&lb;
}

// ---------------------------------------------------------------------------
// Prep kernel (also zeros d_out): per-note MLPs, hann table, output zeroing.
// Grid sized to cover D/4 float4 stores; first 1024 threads also do prep.
// ---------------------------------------------------------------------------
__global__ void prep_kernel(
    const float* __restrict__ freq, const float* __restrict__ velocity,
    const float* __restrict__ w1,  const float* __restrict__ b1,
    const float* __restrict__ w2,  const float* __restrict__ b2,
    const float* __restrict__ ws1, const float* __restrict__ bs1,
    const float* __restrict__ ws2, const float* __restrict__ bs2,
    const int*   __restrict__ starts, const int* __restrict__ lengths,
    float* __restrict__ out, int D)
{
    int i = blockIdx.x * blockDim.x + threadIdx.x;

    // zero the output (harness poisons it)
    int n4 = D >> 2;
    if (i < n4) ((float4*)out)[i] = make_float4(0.f, 0.f, 0.f, 0.f);
    int tail = n4 * 4 + i;
    if (i < 4 && tail < D) out[tail] = 0.0f;

    if (i < WW) {
        // exactly replicate reference arg: fl(fl(2pi_f32 * n) / 1024)
        float a = 6.283185307179586f * (float)i * (1.0f / 1024.0f);
        double c = cos((double)a);
        g_hann[i] = 0.5f * (1.0f - (float)c);
    }

    if (i < NN) {
        int st = starts[i];
        int en = st + lengths[i];
        int ol = min(en, D) - st;
        ol = max(0, min(ol, LL));
        g_olen[i] = ol;

        // time embedder: Linear(1,32) -> ReLU -> Linear(32,2)
        float nt = (float)st / (float)D;
        float lat0 = b2[0], lat1 = b2[1];
        #pragma unroll 8
        for (int j = 0; j < 32; ++j) {
            float h = fmaxf(fmaf(nt, w1[j], b1[j]), 0.0f);
            lat0 = fmaf(h, w2[j * 2 + 0], lat0);
            lat1 = fmaf(h, w2[j * 2 + 1], lat1);
        }

        float vel = velocity[i] * (1.0f / 127.0f);
        float feat0 = freq[i], feat1 = vel;

        // synth MLP: (4 -> 64 -> 8), softplus on output
        float z[HH];
        #pragma unroll
        for (int h = 0; h < HH; ++h) z[h] = bs2[h];
        #pragma unroll 4
        for (int j = 0; j < 64; ++j) {
            float h2 = bs1[j];
            h2 = fmaf(feat0, ws1[0 * 64 + j], h2);
            h2 = fmaf(feat1, ws1[1 * 64 + j], h2);
            h2 = fmaf(lat0,  ws1[2 * 64 + j], h2);
            h2 = fmaf(lat1,  ws1[3 * 64 + j], h2);
            h2 = fmaxf(h2, 0.0f);
            #pragma unroll
            for (int h = 0; h < HH; ++h)
                z[h] = fmaf(h2, ws2[j * HH + h], z[h]);
        }
        #pragma unroll
        for (int h = 0; h < HH; ++h) {
            float zz = z[h];
            float sp = fmaxf(zz, 0.0f) + log1pf(__expf(-fabsf(zz)));
            g_amps[i * HH + h] = sp * vel;            // fold vel into amps
        }
    }
}

// ---------------------------------------------------------------------------
// Main kernel.
// Phase 0: Toeplitz FIR matrix Fe[p][j] = fir[j-p] (16 x 144), hi/lo bf16.
// Phase 1: scalar synthesis of windowed/masked segment (bit-matches ref args),
//          stored as hi/lo bf16 split arrays.
// Phase 2: FIR as tensor-core GEMM: y[b*16+p] = sum_j Fe[p][j] * s[b*16+j]
//          via mma.sync.m16n8k16 (bf16 -> fp32), 3 split products (hh,hl,lh).
// Phase 3: COALESCED tanh + RED.ADD scatter (thread tid owns {tid + 256m}).
//
// jax conv is CROSS-CORRELATION with left pad (K-1):
//   y[r] = sum_{k=0..127} fir[k] * s[r + k],  s[e] = x(t0 - 127 + e)
// ---------------------------------------------------------------------------
__device__ __forceinline__ void mma_bf16(float& d0, float& d1, float& d2, float& d3,
                                         unsigned int a0, unsigned int a1,
                                         unsigned int a2, unsigned int a3,
                                         unsigned int b0, unsigned int b1) {
    asm volatile(
        "mma.sync.aligned.m16n8k16.row.col.f32.bf16.bf16.f32 "
        "{%0,%1,%2,%3}, {%4,%5,%6,%7}, {%8,%9}, {%0,%1,%2,%3};"
        : "+f"(d0), "+f"(d1), "+f"(d2), "+f"(d3)
        : "r"(a0), "r"(a1), "r"(a2), "r"(a3), "r"(b0), "r"(b1));
}

__global__ void __launch_bounds__(NTHREADS)
synth_kernel(const float* __restrict__ freq,
             const int*   __restrict__ starts,
             const float* __restrict__ fir,
             float*       __restrict__ out)
{
    const int note = blockIdx.y;
    const int olen = g_olen[note];
    const int t0   = blockIdx.x * TILE;
    if (t0 >= olen) return;                  // uniform early exit

    __shared__ unsigned short s_h[SEG], s_l[SEG];          // segment hi/lo bf16
    __shared__ unsigned short feh[16 * KPAD], fel[16 * KPAD];
    __shared__ float y_s[TILE];

    const int tid = threadIdx.x;

    // ---- phase 0: Toeplitz FIR matrix, split bf16 ----
    for (int idx = tid; idx < 16 * KPAD; idx += NTHREADS) {
        int p = idx / KPAD, j = idx - p * KPAD;
        int d = j - p;
        float v = (d >= 0 && d < KK) ? __ldg(&fir[d]) : 0.0f;
        unsigned short h, l;
        split_bf16(v, h, l);
        feh[idx] = h;
        fel[idx] = l;
    }

    // per-note constants (uniform loads)
    const float f0 = __ldg(&freq[note]);
    const int   start = __ldg(&starts[note]);
    float amp[HH];
    #pragma unroll
    for (int h = 0; h < HH; ++h) amp[h] = __ldg(&g_amps[note * HH + h]);

    // ---- phase 1: synthesize windowed/masked segment, split bf16 ----
    const int wstart = olen - WW;
    for (int e = tid; e < SEG; e += NTHREADS) {
        int t = t0 - 127 + e;
        float v = 0.0f;
        if (t >= 0 && t < olen) {
            float ph = f0 * (float)t;        // matches ref fp32 phase
            float acc = 0.0f;
            #pragma unroll
            for (int h = 1; h <= HH; ++h) {
                float arg = (float)h * ph;   // matches ref fl(h*phase)
                acc = fmaf(amp[h - 1], sin_ref(arg), acc);
            }
            int wpos = t - wstart;
            if (wpos >= 0) acc *= g_hann[wpos];   // wpos < WW guaranteed
            v = acc;
        }
        unsigned short hh, ll;
        split_bf16(v, hh, ll);
        s_h[e] = hh;
        s_l[e] = ll;
    }
    __syncthreads();

    // ---- phase 2: FIR via mma.sync, 2 n-groups of 8 blocks per warp ----
    {
        const int lane = tid & 31;
        const int w    = tid >> 5;
        const int rr   = lane >> 2;          // 0..7 (A row / B col group)
        const int kq   = (lane & 3) << 1;    // 0,2,4,6 (k pair offset)

        float d0[2] = {0.f, 0.f}, d1[2] = {0.f, 0.f};
        float d2[2] = {0.f, 0.f}, d3[2] = {0.f, 0.f};

        #pragma unroll
        for (int q = 0; q < 9; ++q) {
            const int ja = q * 16 + kq;
            // A fragments (Fe) — shared across both n-groups (hoisted)
            unsigned int ah0 = *(const unsigned int*)&feh[ rr      * KPAD + ja];
            unsigned int ah1 = *(const unsigned int*)&feh[(rr + 8) * KPAD + ja];
            unsigned int ah2 = *(const unsigned int*)&feh[ rr      * KPAD + ja + 8];
            unsigned int ah3 = *(const unsigned int*)&feh[(rr + 8) * KPAD + ja + 8];
            unsigned int al0 = *(const unsigned int*)&fel[ rr      * KPAD + ja];
            unsigned int al1 = *(const unsigned int*)&fel[(rr + 8) * KPAD + ja];
            unsigned int al2 = *(const unsigned int*)&fel[ rr      * KPAD + ja + 8];
            unsigned int al3 = *(const unsigned int*)&fel[(rr + 8) * KPAD + ja + 8];

            #pragma unroll
            for (int g2 = 0; g2 < 2; ++g2) {
                const int g = w * 2 + g2;            // n-group: blocks g*8..g*8+7
                const int bbase = g * 128 + rr * 16; // + k
                unsigned int bh0 = *(const unsigned int*)&s_h[bbase + ja];
                unsigned int bh1 = *(const unsigned int*)&s_h[bbase + ja + 8];
                unsigned int bl0 = *(const unsigned int*)&s_l[bbase + ja];
                unsigned int bl1 = *(const unsigned int*)&s_l[bbase + ja + 8];

                mma_bf16(d0[g2], d1[g2], d2[g2], d3[g2], ah0, ah1, ah2, ah3, bh0, bh1);
                mma_bf16(d0[g2], d1[g2], d2[g2], d3[g2], ah0, ah1, ah2, ah3, bl0, bl1);
                mma_bf16(d0[g2], d1[g2], d2[g2], d3[g2], al0, al1, al2, al3, bh0, bh1);
            }
        }
        // D frag: row p = rr (+8), col n = (lane&3)*2 (+1); y idx = (g*8+n)*16+p
        const int col = (lane & 3) << 1;
        #pragma unroll
        for (int g2 = 0; g2 < 2; ++g2) {
            const int g = w * 2 + g2;
            const int base = (g * 8 + col) * 16 + rr;
            y_s[base]      = d0[g2];     // (p=rr,   n=col)
            y_s[base + 16] = d1[g2];     // (p=rr,   n=col+1)
            y_s[base + 8]  = d2[g2];     // (p=rr+8, n=col)
            y_s[base + 24] = d3[g2];     // (p=rr+8, n=col+1)
        }
    }
    __syncthreads();

    // ---- phase 3: coalesced tanh + scatter-add ----
    // thread tid owns outputs {tid + 256m}: warp lanes consecutive -> each
    // RED.ADD instruction touches one 128B line instead of 32 sectors.
    const int limit = olen - t0;             // valid outputs: r < limit
    float* __restrict__ gbase = out + start + t0;
    #pragma unroll
    for (int m = 0; m < OPT; ++m) {
        int r = tid + NTHREADS * m;
        if (r < limit)
            atomicAdd(gbase + r, tanh_ref(y_s[r]));   // RED.ADD, coalesced
    }
}

// ---------------------------------------------------------------------------
// Launch: prep(+zero) -> synth (same stream, graph-capturable)
// ---------------------------------------------------------------------------
extern "C" void kernel_launch(void* const* d_in, const int* in_sizes, int n_in,
                              void* d_out, int out_size) {
    const float* freq     = (const float*)d_in[0];
    const float* velocity = (const float*)d_in[1];
    const float* w1       = (const float*)d_in[2];
    const float* b1       = (const float*)d_in[3];
    const float* w2       = (const float*)d_in[4];
    const float* b2       = (const float*)d_in[5];
    const float* ws1      = (const float*)d_in[6];
    const float* bs1      = (const float*)d_in[7];
    const float* ws2      = (const float*)d_in[8];
    const float* bs2      = (const float*)d_in[9];
    const float* fir      = (const float*)d_in[10];
    const int*   starts   = (const int*)d_in[11];
    const int*   lengths  = (const int*)d_in[12];
    float* out = (float*)d_out;
    const int D = out_size;                  // duration_samples == out_size

    int nblk = (D / 4 + NTHREADS - 1) / NTHREADS + 1;   // covers zeroing + prep
    prep_kernel<<<nblk, NTHREADS>>>(freq, velocity, w1, b1, w2, b2,
                                    ws1, bs1, ws2, bs2, starts, lengths, out, D);
    dim3 grid(LL / TILE, NN);                // 16 x 1024 blocks, early-exit culls
    synth_kernel<<<grid, NTHREADS>>>(freq, starts, fir, out);
}

// round 10
// speedup vs baseline: 1.5735x; 1.0679x over previous
#include <cuda_runtime.h>
#include <cuda_bf16.h>
#include <math.h>
#include <stdint.h>

// Problem constants (fixed shapes for this problem instance)
#define NN   1024     // notes
#define LL   32768    // max note length
#define WW   1024     // hann window length
#define HH   8        // harmonics
#define KK   128      // FIR taps
#define TILE 2048     // output samples per block
#define NTHREADS 256
#define OPT  8        // outputs per thread in epilogue

#define SEG   2176    // s indices [0, 2175]: covers b*16 + j, b<128, j<144
#define KPAD  144     // logical K (9 k-steps of 16)
#define KPAD2 152     // padded row stride (304B) -> conflict-free LDSM rows

// Scratch (device globals; no allocation allowed)
__device__ float g_amps[NN * HH];   // softplus(z) * vel, per note per harmonic
__device__ float g_hann[WW];
__device__ int   g_olen[NN];

// ---------------------------------------------------------------------------
// Accurate sin of an fp32 argument, |x| < ~1e5.
// k via magic-constant RN-even round (no FRND), 3-term Cody-Waite, MUFU sin.
// ---------------------------------------------------------------------------
__device__ __forceinline__ float sin_ref(float x) {
    const float INV2PI = 0.15915494309189535f;
    const float MAGIC  = 12582912.0f;                 // 1.5 * 2^23
    float k = fmaf(x, INV2PI, MAGIC) - MAGIC;         // rint-even(x/2pi)
    float r = fmaf(k, -6.28125f, x);
    r = fmaf(k, -1.9359588623046875e-3f, r);
    r = fmaf(k,  6.5168271821061e-7f,  r);
    return __sinf(r);
}

// Accurate-enough tanh, flag-independent (avoid tanh.approx ~2^-10 error).
__device__ __forceinline__ float tanh_ref(float x) {
    float ax = fabsf(x);
    float r;
    if (ax >= 9.0f) {
        r = 1.0f;
    } else {
        float e = __expf(2.0f * ax);
        r = 1.0f - __fdividef(2.0f, e + 1.0f);
    }
    return copysignf(r, x);
}

// hi/lo bf16 split: hi = truncate-to-bf16 (exact), lo = rn-bf16(x - hi)
__device__ __forceinline__ void split_bf16(float x, unsigned short& h, unsigned short& l) {
    unsigned int xb = __float_as_uint(x);
    h = (unsigned short)(xb >> 16);
    float hf = __uint_as_float(xb & 0xFFFF0000u);
    float lf = x - hf;                        // exact
    __nv_bfloat16 lb = __float2bfloat16(lf);  // rn
    l = *(unsigned short*)&lb;
}

__device__ __forceinline__ unsigned int smem_u32(const void* p) {
    unsigned int a;
    asm("{ .reg .u64 t; cvta.to.shared.u64 t, %1; cvt.u32.u64 %0, t; }"
        : "=r"(a) : "l"(p));
    return a;
}

// ---------------------------------------------------------------------------
// Prep kernel (also zeros d_out): per-note MLPs, hann table, output zeroing.
// ---------------------------------------------------------------------------
__global__ void prep_kernel(
    const float* __restrict__ freq, const float* __restrict__ velocity,
    const float* __restrict__ w1,  const float* __restrict__ b1,
    const float* __restrict__ w2,  const float* __restrict__ b2,
    const float* __restrict__ ws1, const float* __restrict__ bs1,
    const float* __restrict__ ws2, const float* __restrict__ bs2,
    const int*   __restrict__ starts, const int* __restrict__ lengths,
    float* __restrict__ out, int D)
{
    int i = blockIdx.x * blockDim.x + threadIdx.x;

    // zero the output (harness poisons it)
    int n4 = D >> 2;
    if (i < n4) ((float4*)out)[i] = make_float4(0.f, 0.f, 0.f, 0.f);
    int tail = n4 * 4 + i;
    if (i < 4 && tail < D) out[tail] = 0.0f;

    if (i < WW) {
        // exactly replicate reference arg: fl(fl(2pi_f32 * n) / 1024)
        float a = 6.283185307179586f * (float)i * (1.0f / 1024.0f);
        double c = cos((double)a);
        g_hann[i] = 0.5f * (1.0f - (float)c);
    }

    if (i < NN) {
        int st = starts[i];
        int en = st + lengths[i];
        int ol = min(en, D) - st;
        ol = max(0, min(ol, LL));
        g_olen[i] = ol;

        // time embedder: Linear(1,32) -> ReLU -> Linear(32,2)
        float nt = (float)st / (float)D;
        float lat0 = b2[0], lat1 = b2[1];
        #pragma unroll 8
        for (int j = 0; j < 32; ++j) {
            float h = fmaxf(fmaf(nt, w1[j], b1[j]), 0.0f);
            lat0 = fmaf(h, w2[j * 2 + 0], lat0);
            lat1 = fmaf(h, w2[j * 2 + 1], lat1);
        }

        float vel = velocity[i] * (1.0f / 127.0f);
        float feat0 = freq[i], feat1 = vel;

        // synth MLP: (4 -> 64 -> 8), softplus on output
        float z[HH];
        #pragma unroll
        for (int h = 0; h < HH; ++h) z[h] = bs2[h];
        #pragma unroll 4
        for (int j = 0; j < 64; ++j) {
            float h2 = bs1[j];
            h2 = fmaf(feat0, ws1[0 * 64 + j], h2);
            h2 = fmaf(feat1, ws1[1 * 64 + j], h2);
            h2 = fmaf(lat0,  ws1[2 * 64 + j], h2);
            h2 = fmaf(lat1,  ws1[3 * 64 + j], h2);
            h2 = fmaxf(h2, 0.0f);
            #pragma unroll
            for (int h = 0; h < HH; ++h)
                z[h] = fmaf(h2, ws2[j * HH + h], z[h]);
        }
        #pragma unroll
        for (int h = 0; h < HH; ++h) {
            float zz = z[h];
            float sp = fmaxf(zz, 0.0f) + log1pf(__expf(-fabsf(zz)));
            g_amps[i * HH + h] = sp * vel;            // fold vel into amps
        }
    }
}

// ---------------------------------------------------------------------------
// Main kernel.
// Phase 0: Toeplitz FIR matrix Fe[p][j] = fir[j-p] (16 x 144, stride 152),
//          hi/lo bf16 split.
// Phase 1: scalar synthesis (bit-matches ref arg quantization), 2 samples
//          per thread, packed STS.32 into hi/lo bf16 arrays.
// Phase 2: FIR as tensor-core GEMM via ldmatrix.x4 + mma.m16n8k16 bf16,
//          3 split products (hh, hl, lh).
// Phase 3: coalesced tanh + scalar RED.ADD scatter (proven R7 path).
//
// jax conv is CROSS-CORRELATION with left pad (K-1):
//   y[r] = sum_{k=0..127} fir[k] * s[r + k],  s[e] = x(t0 - 127 + e)
// ---------------------------------------------------------------------------
__device__ __forceinline__ void mma_bf16(float& d0, float& d1, float& d2, float& d3,
                                         unsigned int a0, unsigned int a1,
                                         unsigned int a2, unsigned int a3,
                                         unsigned int b0, unsigned int b1) {
    asm volatile(
        "mma.sync.aligned.m16n8k16.row.col.f32.bf16.bf16.f32 "
        "{%0,%1,%2,%3}, {%4,%5,%6,%7}, {%8,%9}, {%0,%1,%2,%3};"
        : "+f"(d0), "+f"(d1), "+f"(d2), "+f"(d3)
        : "r"(a0), "r"(a1), "r"(a2), "r"(a3), "r"(b0), "r"(b1));
}

#define LDSM_X4(r0, r1, r2, r3, addr) \
    asm volatile("ldmatrix.sync.aligned.m8n8.x4.shared.b16 {%0,%1,%2,%3}, [%4];" \
        : "=r"(r0), "=r"(r1), "=r"(r2), "=r"(r3) : "r"(addr))

__global__ void __launch_bounds__(NTHREADS)
synth_kernel(const float* __restrict__ freq,
             const int*   __restrict__ starts,
             const float* __restrict__ fir,
             float*       __restrict__ out)
{
    const int note = blockIdx.y;
    const int olen = g_olen[note];
    const int t0   = blockIdx.x * TILE;
    if (t0 >= olen) return;                  // uniform early exit

    // ldmatrix: every lane row address must be 16B-aligned -> align the bases.
    __shared__ __align__(16) unsigned short s_h[SEG], s_l[SEG];
    __shared__ __align__(16) unsigned short feh[16 * KPAD2], fel[16 * KPAD2];
    __shared__ __align__(16) float y_s[TILE];

    const int tid = threadIdx.x;

    // ---- phase 0: Toeplitz FIR matrix, split bf16 (zero padding incl.) ----
    for (int idx = tid; idx < 16 * KPAD2; idx += NTHREADS) {
        int p = idx / KPAD2, j = idx - p * KPAD2;
        int d = j - p;
        float v = (j < KPAD && d >= 0 && d < KK) ? __ldg(&fir[d]) : 0.0f;
        unsigned short h, l;
        split_bf16(v, h, l);
        feh[idx] = h;
        fel[idx] = l;
    }

    // per-note constants (uniform loads)
    const float f0 = __ldg(&freq[note]);
    const int   start = __ldg(&starts[note]);
    float amp[HH];
    #pragma unroll
    for (int h = 0; h < HH; ++h) amp[h] = __ldg(&g_amps[note * HH + h]);

    // ---- phase 1: synthesize 2 samples/thread, packed STS.32 ----
    const int wstart = olen - WW;
    for (int p = tid; p < SEG / 2; p += NTHREADS) {
        const int e = 2 * p;
        float v01[2];
        #pragma unroll
        for (int u = 0; u < 2; ++u) {
            int t = t0 - 127 + e + u;
            float v = 0.0f;
            if ((unsigned)t < (unsigned)olen) {
                float ph = f0 * (float)t;    // matches ref fp32 phase
                float acc = 0.0f;
                #pragma unroll
                for (int h = 1; h <= HH; ++h) {
                    float arg = (float)h * ph;   // matches ref fl(h*phase)
                    acc = fmaf(amp[h - 1], sin_ref(arg), acc);
                }
                int wpos = t - wstart;
                if (wpos >= 0) acc *= g_hann[wpos];
                v = acc;
            }
            v01[u] = v;
        }
        unsigned int b0 = __float_as_uint(v01[0]);
        unsigned int b1 = __float_as_uint(v01[1]);
        // hi word: bytes {b0.2, b0.3, b1.2, b1.3}
        unsigned int hw = __byte_perm(b0, b1, 0x7632);
        // lo parts: exact residual, rn to bf16, packed
        float lo0 = v01[0] - __uint_as_float(b0 & 0xFFFF0000u);
        float lo1 = v01[1] - __uint_as_float(b1 & 0xFFFF0000u);
        __nv_bfloat162 lp = __floats2bfloat162_rn(lo0, lo1);
        *(unsigned int*)&s_h[e] = hw;
        *(unsigned int*)&s_l[e] = *(unsigned int*)&lp;
    }
    __syncthreads();

    // ---- phase 2: FIR via ldmatrix + mma, 2 n-groups per warp ----
    {
        const int lane = tid & 31;
        const int w    = tid >> 5;

        // A lane address: tile = lane>>3; tiles {rows0-7,k0-7},{rows8-15,k0-7},
        //                 {rows0-7,k8-15},{rows8-15,k8-15}
        const int tA = lane >> 3;
        const int rowA = (lane & 7) + ((tA & 1) << 3);
        const int kA = (tA >> 1) << 3;
        unsigned int aH = smem_u32(&feh[rowA * KPAD2 + kA]);
        unsigned int aL = smem_u32(&fel[rowA * KPAD2 + kA]);

        // B lane address: tiles {g0,k0-7},{g0,k8-15},{g1,k0-7},{g1,k8-15}
        const int tB = lane >> 3;
        const int gB = tB >> 1, ktB = tB & 1, nrB = lane & 7;
        const int bidx = ((w * 2 + gB) * 8 + nrB) * 16 + ktB * 8;
        unsigned int bH = smem_u32(&s_h[bidx]);
        unsigned int bL = smem_u32(&s_l[bidx]);

        float d0[2] = {0.f, 0.f}, d1[2] = {0.f, 0.f};
        float d2[2] = {0.f, 0.f}, d3[2] = {0.f, 0.f};

        #pragma unroll
        for (int q = 0; q < 9; ++q) {
            unsigned int ah0, ah1, ah2, ah3, al0, al1, al2, al3;
            LDSM_X4(ah0, ah1, ah2, ah3, aH); aH += 32;
            LDSM_X4(al0, al1, al2, al3, aL); aL += 32;
            unsigned int bh[4], bl[4];
            LDSM_X4(bh[0], bh[1], bh[2], bh[3], bH); bH += 32;
            LDSM_X4(bl[0], bl[1], bl[2], bl[3], bL); bL += 32;

            #pragma unroll
            for (int g2 = 0; g2 < 2; ++g2) {
                mma_bf16(d0[g2], d1[g2], d2[g2], d3[g2],
                         ah0, ah1, ah2, ah3, bh[2 * g2], bh[2 * g2 + 1]);  // hh
                mma_bf16(d0[g2], d1[g2], d2[g2], d3[g2],
                         ah0, ah1, ah2, ah3, bl[2 * g2], bl[2 * g2 + 1]);  // hl
                mma_bf16(d0[g2], d1[g2], d2[g2], d3[g2],
                         al0, al1, al2, al3, bh[2 * g2], bh[2 * g2 + 1]);  // lh
            }
        }
        // D frag: row p = rr (+8), col n = (lane&3)*2 (+1); y idx = (g*8+n)*16+p
        const int rr  = lane >> 2;
        const int col = (lane & 3) << 1;
        #pragma unroll
        for (int g2 = 0; g2 < 2; ++g2) {
            const int g = w * 2 + g2;
            const int base = (g * 8 + col) * 16 + rr;
            y_s[base]      = d0[g2];     // (p=rr,   n=col)
            y_s[base + 16] = d1[g2];     // (p=rr,   n=col+1)
            y_s[base + 8]  = d2[g2];     // (p=rr+8, n=col)
            y_s[base + 24] = d3[g2];     // (p=rr+8, n=col+1)
        }
    }
    __syncthreads();

    // ---- phase 3: coalesced tanh + scalar scatter-add (proven R7 path) ----
    // thread tid owns outputs {tid + 256m}: warp lanes consecutive -> each
    // RED.ADD instruction touches one 128B line instead of 32 sectors.
    const int limit = olen - t0;             // valid outputs: r < limit
    float* __restrict__ gbase = out + start + t0;
    #pragma unroll
    for (int m = 0; m < OPT; ++m) {
        int r = tid + NTHREADS * m;
        if (r < limit)
            atomicAdd(gbase + r, tanh_ref(y_s[r]));   // RED.ADD, coalesced
    }
}

// ---------------------------------------------------------------------------
// Launch: prep(+zero) -> synth (same stream, graph-capturable)
// ---------------------------------------------------------------------------
extern "C" void kernel_launch(void* const* d_in, const int* in_sizes, int n_in,
                              void* d_out, int out_size) {
    const float* freq     = (const float*)d_in[0];
    const float* velocity = (const float*)d_in[1];
    const float* w1       = (const float*)d_in[2];
    const float* b1       = (const float*)d_in[3];
    const float* w2       = (const float*)d_in[4];
    const float* b2       = (const float*)d_in[5];
    const float* ws1      = (const float*)d_in[6];
    const float* bs1      = (const float*)d_in[7];
    const float* ws2      = (const float*)d_in[8];
    const float* bs2      = (const float*)d_in[9];
    const float* fir      = (const float*)d_in[10];
    const int*   starts   = (const int*)d_in[11];
    const int*   lengths  = (const int*)d_in[12];
    float* out = (float*)d_out;
    const int D = out_size;                  // duration_samples == out_size

    int nblk = (D / 4 + NTHREADS - 1) / NTHREADS + 1;   // covers zeroing + prep
    prep_kernel<<<nblk, NTHREADS>>>(freq, velocity, w1, b1, w2, b2,
                                    ws1, bs1, ws2, bs2, starts, lengths, out, D);
    dim3 grid(LL / TILE, NN);                // 16 x 1024 blocks, early-exit culls
    synth_kernel<<<grid, NTHREADS>>>(freq, starts, fir, out);
}

// round 11
// speedup vs baseline: 1.7437x; 1.1082x over previous
#include <cuda_runtime.h>
#include <cuda_bf16.h>
#include <math.h>
#include <stdint.h>

// Problem constants (fixed shapes for this problem instance)
#define NN   1024     // notes
#define LL   32768    // max note length
#define WW   1024     // hann window length
#define HH   8        // harmonics
#define KK   128      // FIR taps
#define TILE 2048     // output samples per block
#define NTHREADS 256
#define OPT  8        // outputs per thread in epilogue

#define SEG   2176    // s indices [0, 2175]: covers b*16 + j, b<128, j<144
#define KPAD  144     // logical K (9 k-steps of 16)
#define KPAD2 152     // padded row stride (304B) -> conflict-free LDSM rows
#define FE_ELEMS (16 * KPAD2)       // 2432 shorts = 304 uint4

// Scratch (device globals; no allocation allowed)
__device__ float g_amps[NN * HH];   // softplus(z) * vel, per note per harmonic
__device__ float g_hann[WW];
__device__ int   g_olen[NN];
__device__ __align__(16) unsigned short g_feh[FE_ELEMS];  // Toeplitz hi image
__device__ __align__(16) unsigned short g_fel[FE_ELEMS];  // Toeplitz lo image

// ---------------------------------------------------------------------------
// Accurate sin of an fp32 argument, |x| < ~1e5.
// k via magic-constant RN-even round (no FRND), 3-term Cody-Waite, MUFU sin.
// ---------------------------------------------------------------------------
__device__ __forceinline__ float sin_ref(float x) {
    const float INV2PI = 0.15915494309189535f;
    const float MAGIC  = 12582912.0f;                 // 1.5 * 2^23
    float k = fmaf(x, INV2PI, MAGIC) - MAGIC;         // rint-even(x/2pi)
    float r = fmaf(k, -6.28125f, x);
    r = fmaf(k, -1.9359588623046875e-3f, r);
    r = fmaf(k,  6.5168271821061e-7f,  r);
    return __sinf(r);
}

// Accurate-enough tanh, branch-free (clamp at 9: error <= 1.3e-8).
__device__ __forceinline__ float tanh_ref(float x) {
    float ax = fminf(fabsf(x), 9.0f);
    float e = __expf(2.0f * ax);
    float r = 1.0f - __fdividef(2.0f, e + 1.0f);
    return copysignf(r, x);
}

// hi/lo bf16 split: hi = truncate-to-bf16 (exact), lo = rn-bf16(x - hi)
__device__ __forceinline__ void split_bf16(float x, unsigned short& h, unsigned short& l) {
    unsigned int xb = __float_as_uint(x);
    h = (unsigned short)(xb >> 16);
    float hf = __uint_as_float(xb & 0xFFFF0000u);
    float lf = x - hf;                        // exact
    __nv_bfloat16 lb = __float2bfloat16(lf);  // rn
    l = *(unsigned short*)&lb;
}

__device__ __forceinline__ unsigned int smem_u32(const void* p) {
    unsigned int a;
    asm("{ .reg .u64 t; cvta.to.shared.u64 t, %1; cvt.u32.u64 %0, t; }"
        : "=r"(a) : "l"(p));
    return a;
}

// ---------------------------------------------------------------------------
// Prep kernel (also zeros d_out): per-note MLPs, hann table, Toeplitz image,
// output zeroing.
// ---------------------------------------------------------------------------
__global__ void prep_kernel(
    const float* __restrict__ freq, const float* __restrict__ velocity,
    const float* __restrict__ w1,  const float* __restrict__ b1,
    const float* __restrict__ w2,  const float* __restrict__ b2,
    const float* __restrict__ ws1, const float* __restrict__ bs1,
    const float* __restrict__ ws2, const float* __restrict__ bs2,
    const float* __restrict__ fir,
    const int*   __restrict__ starts, const int* __restrict__ lengths,
    float* __restrict__ out, int D)
{
    int i = blockIdx.x * blockDim.x + threadIdx.x;

    // zero the output (harness poisons it)
    int n4 = D >> 2;
    if (i < n4) ((float4*)out)[i] = make_float4(0.f, 0.f, 0.f, 0.f);
    int tail = n4 * 4 + i;
    if (i < 4 && tail < D) out[tail] = 0.0f;

    // Toeplitz FIR image, split bf16, exact smem layout (stride KPAD2)
    if (i < FE_ELEMS) {
        int p = i / KPAD2, j = i - p * KPAD2;
        int d = j - p;
        float v = (j < KPAD && d >= 0 && d < KK) ? fir[d] : 0.0f;
        unsigned short h, l;
        split_bf16(v, h, l);
        g_feh[i] = h;
        g_fel[i] = l;
    }

    if (i < WW) {
        // exactly replicate reference arg: fl(fl(2pi_f32 * n) / 1024)
        float a = 6.283185307179586f * (float)i * (1.0f / 1024.0f);
        double c = cos((double)a);
        g_hann[i] = 0.5f * (1.0f - (float)c);
    }

    if (i < NN) {
        int st = starts[i];
        int en = st + lengths[i];
        int ol = min(en, D) - st;
        ol = max(0, min(ol, LL));
        g_olen[i] = ol;

        // time embedder: Linear(1,32) -> ReLU -> Linear(32,2)
        float nt = (float)st / (float)D;
        float lat0 = b2[0], lat1 = b2[1];
        #pragma unroll 8
        for (int j = 0; j < 32; ++j) {
            float h = fmaxf(fmaf(nt, w1[j], b1[j]), 0.0f);
            lat0 = fmaf(h, w2[j * 2 + 0], lat0);
            lat1 = fmaf(h, w2[j * 2 + 1], lat1);
        }

        float vel = velocity[i] * (1.0f / 127.0f);
        float feat0 = freq[i], feat1 = vel;

        // synth MLP: (4 -> 64 -> 8), softplus on output
        float z[HH];
        #pragma unroll
        for (int h = 0; h < HH; ++h) z[h] = bs2[h];
        #pragma unroll 4
        for (int j = 0; j < 64; ++j) {
            float h2 = bs1[j];
            h2 = fmaf(feat0, ws1[0 * 64 + j], h2);
            h2 = fmaf(feat1, ws1[1 * 64 + j], h2);
            h2 = fmaf(lat0,  ws1[2 * 64 + j], h2);
            h2 = fmaf(lat1,  ws1[3 * 64 + j], h2);
            h2 = fmaxf(h2, 0.0f);
            #pragma unroll
            for (int h = 0; h < HH; ++h)
                z[h] = fmaf(h2, ws2[j * HH + h], z[h]);
        }
        #pragma unroll
        for (int h = 0; h < HH; ++h) {
            float zz = z[h];
            float sp = fmaxf(zz, 0.0f) + log1pf(__expf(-fabsf(zz)));
            g_amps[i * HH + h] = sp * vel;            // fold vel into amps
        }
    }
}

// ---------------------------------------------------------------------------
// Main kernel.
// Phase 0: copy precomputed Toeplitz split-bf16 images into smem (uint4).
// Phase 1: scalar synthesis (bit-matches ref arg quantization), 2 samples
//          per thread, packed STS.32 into hi/lo bf16 arrays.
// Phase 2: FIR as tensor-core GEMM via ldmatrix.x4 + mma.m16n8k16 bf16,
//          3 split products (hh, hl, lh).
// Phase 3: coalesced tanh + scalar RED.ADD scatter.
//
// jax conv is CROSS-CORRELATION with left pad (K-1):
//   y[r] = sum_{k=0..127} fir[k] * s[r + k],  s[e] = x(t0 - 127 + e)
// ---------------------------------------------------------------------------
__device__ __forceinline__ void mma_bf16(float& d0, float& d1, float& d2, float& d3,
                                         unsigned int a0, unsigned int a1,
                                         unsigned int a2, unsigned int a3,
                                         unsigned int b0, unsigned int b1) {
    asm volatile(
        "mma.sync.aligned.m16n8k16.row.col.f32.bf16.bf16.f32 "
        "{%0,%1,%2,%3}, {%4,%5,%6,%7}, {%8,%9}, {%0,%1,%2,%3};"
        : "+f"(d0), "+f"(d1), "+f"(d2), "+f"(d3)
        : "r"(a0), "r"(a1), "r"(a2), "r"(a3), "r"(b0), "r"(b1));
}

#define LDSM_X4(r0, r1, r2, r3, addr) \
    asm volatile("ldmatrix.sync.aligned.m8n8.x4.shared.b16 {%0,%1,%2,%3}, [%4];" \
        : "=r"(r0), "=r"(r1), "=r"(r2), "=r"(r3) : "r"(addr))

__global__ void __launch_bounds__(NTHREADS)
synth_kernel(const float* __restrict__ freq,
             const int*   __restrict__ starts,
             float*       __restrict__ out)
{
    const int note = blockIdx.y;
    const int olen = g_olen[note];
    const int t0   = blockIdx.x * TILE;
    if (t0 >= olen) return;                  // uniform early exit

    // ldmatrix: every lane row address must be 16B-aligned -> align the bases.
    __shared__ __align__(16) unsigned short s_h[SEG], s_l[SEG];
    __shared__ __align__(16) unsigned short feh[FE_ELEMS], fel[FE_ELEMS];
    __shared__ __align__(16) float y_s[TILE];

    const int tid = threadIdx.x;

    // ---- phase 0: vectorized copy of precomputed Toeplitz images ----
    {
        const uint4* __restrict__ gh = (const uint4*)g_feh;
        const uint4* __restrict__ gl = (const uint4*)g_fel;
        uint4* sh = (uint4*)feh;
        uint4* sl = (uint4*)fel;
        #pragma unroll
        for (int i = tid; i < FE_ELEMS / 8; i += NTHREADS) {   // 304 uint4
            sh[i] = gh[i];
            sl[i] = gl[i];
        }
    }

    // per-note constants (uniform loads)
    const float f0 = __ldg(&freq[note]);
    const int   start = __ldg(&starts[note]);
    float amp[HH];
    #pragma unroll
    for (int h = 0; h < HH; ++h) amp[h] = __ldg(&g_amps[note * HH + h]);

    // ---- phase 1: synthesize 2 samples/thread, packed STS.32 ----
    const int wstart = olen - WW;
    for (int p = tid; p < SEG / 2; p += NTHREADS) {
        const int e = 2 * p;
        float v01[2];
        #pragma unroll
        for (int u = 0; u < 2; ++u) {
            int t = t0 - 127 + e + u;
            float v = 0.0f;
            if ((unsigned)t < (unsigned)olen) {
                float ph = f0 * (float)t;    // matches ref fp32 phase
                float acc = 0.0f;
                #pragma unroll
                for (int h = 1; h <= HH; ++h) {
                    float arg = (float)h * ph;   // matches ref fl(h*phase)
                    acc = fmaf(amp[h - 1], sin_ref(arg), acc);
                }
                int wpos = t - wstart;
                if (wpos >= 0) acc *= g_hann[wpos];
                v = acc;
            }
            v01[u] = v;
        }
        unsigned int b0 = __float_as_uint(v01[0]);
        unsigned int b1 = __float_as_uint(v01[1]);
        // hi word: bytes {b0.2, b0.3, b1.2, b1.3}
        unsigned int hw = __byte_perm(b0, b1, 0x7632);
        // lo parts: exact residual, rn to bf16, packed
        float lo0 = v01[0] - __uint_as_float(b0 & 0xFFFF0000u);
        float lo1 = v01[1] - __uint_as_float(b1 & 0xFFFF0000u);
        __nv_bfloat162 lp = __floats2bfloat162_rn(lo0, lo1);
        *(unsigned int*)&s_h[e] = hw;
        *(unsigned int*)&s_l[e] = *(unsigned int*)&lp;
    }
    __syncthreads();

    // ---- phase 2: FIR via ldmatrix + mma, 2 n-groups per warp ----
    {
        const int lane = tid & 31;
        const int w    = tid >> 5;

        // A lane address: tile = lane>>3; tiles {rows0-7,k0-7},{rows8-15,k0-7},
        //                 {rows0-7,k8-15},{rows8-15,k8-15}
        const int tA = lane >> 3;
        const int rowA = (lane & 7) + ((tA & 1) << 3);
        const int kA = (tA >> 1) << 3;
        unsigned int aH = smem_u32(&feh[rowA * KPAD2 + kA]);
        unsigned int aL = smem_u32(&fel[rowA * KPAD2 + kA]);

        // B lane address: tiles {g0,k0-7},{g0,k8-15},{g1,k0-7},{g1,k8-15}
        const int tB = lane >> 3;
        const int gB = tB >> 1, ktB = tB & 1, nrB = lane & 7;
        const int bidx = ((w * 2 + gB) * 8 + nrB) * 16 + ktB * 8;
        unsigned int bH = smem_u32(&s_h[bidx]);
        unsigned int bL = smem_u32(&s_l[bidx]);

        float d0[2] = {0.f, 0.f}, d1[2] = {0.f, 0.f};
        float d2[2] = {0.f, 0.f}, d3[2] = {0.f, 0.f};

        #pragma unroll
        for (int q = 0; q < 9; ++q) {
            unsigned int ah0, ah1, ah2, ah3, al0, al1, al2, al3;
            LDSM_X4(ah0, ah1, ah2, ah3, aH); aH += 32;
            LDSM_X4(al0, al1, al2, al3, aL); aL += 32;
            unsigned int bh[4], bl[4];
            LDSM_X4(bh[0], bh[1], bh[2], bh[3], bH); bH += 32;
            LDSM_X4(bl[0], bl[1], bl[2], bl[3], bL); bL += 32;

            #pragma unroll
            for (int g2 = 0; g2 < 2; ++g2) {
                mma_bf16(d0[g2], d1[g2], d2[g2], d3[g2],
                         ah0, ah1, ah2, ah3, bh[2 * g2], bh[2 * g2 + 1]);  // hh
                mma_bf16(d0[g2], d1[g2], d2[g2], d3[g2],
                         ah0, ah1, ah2, ah3, bl[2 * g2], bl[2 * g2 + 1]);  // hl
                mma_bf16(d0[g2], d1[g2], d2[g2], d3[g2],
                         al0, al1, al2, al3, bh[2 * g2], bh[2 * g2 + 1]);  // lh
            }
        }
        // D frag: row p = rr (+8), col n = (lane&3)*2 (+1); y idx = (g*8+n)*16+p
        const int rr  = lane >> 2;
        const int col = (lane & 3) << 1;
        #pragma unroll
        for (int g2 = 0; g2 < 2; ++g2) {
            const int g = w * 2 + g2;
            const int base = (g * 8 + col) * 16 + rr;
            y_s[base]      = d0[g2];     // (p=rr,   n=col)
            y_s[base + 16] = d1[g2];     // (p=rr,   n=col+1)
            y_s[base + 8]  = d2[g2];     // (p=rr+8, n=col)
            y_s[base + 24] = d3[g2];     // (p=rr+8, n=col+1)
        }
    }
    __syncthreads();

    // ---- phase 3: coalesced tanh + scalar scatter-add ----
    // thread tid owns outputs {tid + 256m}: warp lanes consecutive -> each
    // RED.ADD instruction touches one 128B line instead of 32 sectors.
    const int limit = olen - t0;             // valid outputs: r < limit
    float* __restrict__ gbase = out + start + t0;
    #pragma unroll
    for (int m = 0; m < OPT; ++m) {
        int r = tid + NTHREADS * m;
        if (r < limit)
            atomicAdd(gbase + r, tanh_ref(y_s[r]));   // RED.ADD, coalesced
    }
}

// ---------------------------------------------------------------------------
// Launch: prep(+zero+Toeplitz) -> synth (same stream, graph-capturable)
// ---------------------------------------------------------------------------
extern "C" void kernel_launch(void* const* d_in, const int* in_sizes, int n_in,
                              void* d_out, int out_size) {
    const float* freq     = (const float*)d_in[0];
    const float* velocity = (const float*)d_in[1];
    const float* w1       = (const float*)d_in[2];
    const float* b1       = (const float*)d_in[3];
    const float* w2       = (const float*)d_in[4];
    const float* b2       = (const float*)d_in[5];
    const float* ws1      = (const float*)d_in[6];
    const float* bs1      = (const float*)d_in[7];
    const float* ws2      = (const float*)d_in[8];
    const float* bs2      = (const float*)d_in[9];
    const float* fir      = (const float*)d_in[10];
    const int*   starts   = (const int*)d_in[11];
    const int*   lengths  = (const int*)d_in[12];
    float* out = (float*)d_out;
    const int D = out_size;                  // duration_samples == out_size

    int nblk = (D / 4 + NTHREADS - 1) / NTHREADS + 1;   // covers zeroing + prep
    prep_kernel<<<nblk, NTHREADS>>>(freq, velocity, w1, b1, w2, b2,
                                    ws1, bs1, ws2, bs2, fir,
                                    starts, lengths, out, D);
    dim3 grid(LL / TILE, NN);                // 16 x 1024 blocks, early-exit culls
    synth_kernel<<<grid, NTHREADS>>>(freq, starts, out);
}